// round 1
// baseline (speedup 1.0000x reference)
#include <cuda_runtime.h>
#include <cstdint>
#include <cstddef>

#define NN   4096
#define FIN  512
#define DH   64
#define NH   8
#define NC   16
#define KH   2
#define MAXNBR 512

// ---------------- scratch (device globals; no allocation allowed) ----------
__device__ float g_Wh[(size_t)NH * NN * DH];      // [H,N,D]  8 MB
__device__ float g_f1[NH * NN];
__device__ float g_f2[NH * NN];
__device__ float g_x2[(size_t)NN * NH * DH];      // [N, H*D] 8 MB
__device__ float g_Who[NN * NC];
__device__ float g_g1[NN];
__device__ float g_g2[NN];
__device__ int   g_nbr[(size_t)KH * NN * MAXNBR]; // 16 MB
__device__ int   g_cnt[KH * NN];
__device__ int   g_mask_mode;                     // 0=byte,1=int32,2=float32

// ---------------- mask dtype detection ------------------------------------
// masks[hop][i][i] is guaranteed true (self loops). Check 64 diagonal slots
// under each interpretation; exactly one will be consistently "1".
__global__ void detect_mask_kernel(const void* m) {
    const unsigned char* b = (const unsigned char*)m;
    const int*   ip = (const int*)m;
    const float* fp = (const float*)m;
    bool okb = true, oki = true, okf = true;
    for (int i = 0; i < 64; ++i) {
        size_t idx = (size_t)i * NN + i;
        if (b[idx] != 1)       okb = false;
        if (ip[idx] != 1)      oki = false;
        if (fp[idx] != 1.0f)   okf = false;
    }
    g_mask_mode = okb ? 0 : (oki ? 1 : (okf ? 2 : 0));
}

// ---------------- neighbor list build (deterministic ballot compaction) ----
__global__ void build_nbr_kernel(const void* m) {
    const int gw   = (blockIdx.x * blockDim.x + threadIdx.x) >> 5;
    const int lane = threadIdx.x & 31;
    if (gw >= KH * NN) return;
    const int mode = g_mask_mode;
    const size_t rowbase = (size_t)gw * NN;
    const unsigned char* bp = (const unsigned char*)m + rowbase;
    const int*   ip = (const int*)m + rowbase;
    const float* fp = (const float*)m + rowbase;

    int* nb = g_nbr + (size_t)gw * MAXNBR;
    int cnt = 0;
    for (int c0 = 0; c0 < NN; c0 += 32) {
        int col = c0 + lane;
        bool mv;
        if (mode == 0)      mv = (bp[col] != 0);
        else if (mode == 1) mv = (ip[col] != 0);
        else                mv = (fp[col] != 0.0f);
        unsigned bal = __ballot_sync(0xffffffffu, mv);
        if (mv) {
            int pos = cnt + __popc(bal & ((1u << lane) - 1u));
            if (pos < MAXNBR) nb[pos] = col;
        }
        cnt += __popc(bal);
    }
    if (lane == 0) g_cnt[gw] = cnt < MAXNBR ? cnt : MAXNBR;
}

// ---------------- Wh = x @ W per head (tiled GEMM) -------------------------
#define BM 128
#define BK 32
__global__ void wh_gemm_kernel(const float* __restrict__ x,
                               const float* __restrict__ W) {
    const int h    = blockIdx.y;
    const int row0 = blockIdx.x * BM;
    const int tid  = threadIdx.x;
    const int tx   = tid & 15;          // 16 col groups (4 cols each)
    const int ty   = tid >> 4;          // 16 row groups (8 rows each)

    __shared__ float xs[BM][BK + 1];
    __shared__ float ws[BK][DH];

    float acc[8][4];
#pragma unroll
    for (int i = 0; i < 8; ++i)
#pragma unroll
        for (int j = 0; j < 4; ++j) acc[i][j] = 0.0f;

    for (int k0 = 0; k0 < FIN; k0 += BK) {
        for (int i = tid; i < BM * BK; i += 256) {
            int r = i >> 5, c = i & 31;
            xs[r][c] = x[(size_t)(row0 + r) * FIN + k0 + c];
        }
        for (int i = tid; i < BK * DH; i += 256) {
            int r = i >> 6, c = i & 63;
            ws[r][c] = W[((size_t)h * FIN + k0 + r) * DH + c];
        }
        __syncthreads();
#pragma unroll
        for (int kk = 0; kk < BK; ++kk) {
            float b0 = ws[kk][tx * 4 + 0];
            float b1 = ws[kk][tx * 4 + 1];
            float b2 = ws[kk][tx * 4 + 2];
            float b3 = ws[kk][tx * 4 + 3];
#pragma unroll
            for (int i = 0; i < 8; ++i) {
                float a = xs[ty * 8 + i][kk];
                acc[i][0] += a * b0;
                acc[i][1] += a * b1;
                acc[i][2] += a * b2;
                acc[i][3] += a * b3;
            }
        }
        __syncthreads();
    }
#pragma unroll
    for (int i = 0; i < 8; ++i) {
        size_t base = ((size_t)h * NN + row0 + ty * 8 + i) * DH + tx * 4;
#pragma unroll
        for (int j = 0; j < 4; ++j) g_Wh[base + j] = acc[i][j];
    }
}

// ---------------- f1,f2 = Wh . a1/a2 ---------------------------------------
__global__ void f12_kernel(const float* __restrict__ a1,
                           const float* __restrict__ a2) {
    int t = blockIdx.x * blockDim.x + threadIdx.x;
    if (t >= NH * NN) return;
    int h = t >> 12;
    const float* wh = g_Wh + (size_t)t * DH;
    const float* A1 = a1 + h * DH;
    const float* A2 = a2 + h * DH;
    float s1 = 0.f, s2 = 0.f;
#pragma unroll 8
    for (int d = 0; d < DH; ++d) {
        float v = wh[d];
        s1 += v * A1[d];
        s2 += v * A2[d];
    }
    g_f1[t] = s1;
    g_f2[t] = s2;
}

// ---------------- layer-1 sparse k-hop attention (per h,n block) -----------
__global__ void gat1_kernel() {
    const int b = blockIdx.x;
    const int h = b >> 12;       // / 4096
    const int n = b & 4095;
    const int t = threadIdx.x;   // 0..63, also the output feature index d

    __shared__ float p[MAXNBR];
    __shared__ float red[64];

    const float  f1v = g_f1[h * NN + n];
    const float* f2h = g_f2 + h * NN;
    const float* WhH = g_Wh + (size_t)h * NN * DH;

    float acc = 0.f;
    for (int hop = 0; hop < KH; ++hop) {
        const int  w   = hop * NN + n;
        const int  cnt = g_cnt[w];
        const int* nb  = g_nbr + (size_t)w * MAXNBR;

        // e + local max
        float lmax = -1e30f;
        for (int j = t; j < cnt; j += 64) {
            float v = f1v + f2h[nb[j]];
            v = v > 0.f ? v : 0.2f * v;
            p[j] = v;
            lmax = fmaxf(lmax, v);
        }
        red[t] = lmax;
        __syncthreads();
#pragma unroll
        for (int s = 32; s > 0; s >>= 1) {
            if (t < s) red[t] = fmaxf(red[t], red[t + s]);
            __syncthreads();
        }
        const float mx = red[0];
        __syncthreads();

        // exp + local sum
        float lsum = 0.f;
        for (int j = t; j < cnt; j += 64) {
            float ex = __expf(p[j] - mx);
            p[j] = ex;
            lsum += ex;
        }
        red[t] = lsum;
        __syncthreads();
#pragma unroll
        for (int s = 32; s > 0; s >>= 1) {
            if (t < s) red[t] += red[t + s];
            __syncthreads();
        }
        const float scale = (hop ? 0.9f : 1.0f) / red[0];
        __syncthreads();

        // weighted aggregation: thread t owns feature d=t
        float part = 0.f;
        for (int j = 0; j < cnt; ++j)
            part += p[j] * WhH[(size_t)nb[j] * DH + t];
        acc += scale * part;
        __syncthreads();   // protect p before next hop overwrites
    }
    // ELU + concat store: x2[n, h*D + t]
    float v = acc > 0.f ? acc : (__expf(acc) - 1.f);
    g_x2[(size_t)n * (NH * DH) + h * DH + t] = v;
}

// ---------------- Who = x2 @ W_out, g1/g2 (fused) ---------------------------
__global__ void who_kernel(const float* __restrict__ W_out,
                           const float* __restrict__ a_out1,
                           const float* __restrict__ a_out2) {
    const int n = blockIdx.x;
    const int t = threadIdx.x;        // 128 threads: c = t%16, ks = t/16 (8 strides)
    __shared__ float xs[FIN];
    __shared__ float wsum[128];
    __shared__ float who_s[NC];

    for (int i = t; i < FIN; i += 128) xs[i] = g_x2[(size_t)n * FIN + i];
    __syncthreads();

    const int c = t & 15, ks = t >> 4;
    float s = 0.f;
    for (int k = ks; k < FIN; k += 8) s += xs[k] * W_out[(size_t)k * NC + c];
    wsum[t] = s;
    __syncthreads();

    if (t < NC) {
        float tot = 0.f;
#pragma unroll
        for (int i = 0; i < 8; ++i) tot += wsum[i * 16 + t];
        who_s[t] = tot;
        g_Who[(size_t)n * NC + t] = tot;
    }
    __syncthreads();
    if (t == 0) {
        float g = 0.f;
#pragma unroll
        for (int cc = 0; cc < NC; ++cc) g += who_s[cc] * a_out1[cc];
        g_g1[n] = g;
    }
    if (t == 1) {
        float g = 0.f;
#pragma unroll
        for (int cc = 0; cc < NC; ++cc) g += who_s[cc] * a_out2[cc];
        g_g2[n] = g;
    }
}

// ---------------- output sparse k-hop attention + elu + log_softmax --------
__global__ void out_kernel(float* __restrict__ out) {
    const int n    = blockIdx.x;
    const int lane = threadIdx.x;    // 32 threads = 1 warp
    __shared__ float p[MAXNBR];

    const float g1v = g_g1[n];
    float acc = 0.f;

    for (int hop = 0; hop < KH; ++hop) {
        const int  w   = hop * NN + n;
        const int  cnt = g_cnt[w];
        const int* nb  = g_nbr + (size_t)w * MAXNBR;

        float lmax = -1e30f;
        for (int j = lane; j < cnt; j += 32) {
            float v = g1v + g_g2[nb[j]];
            v = v > 0.f ? v : 0.2f * v;
            p[j] = v;
            lmax = fmaxf(lmax, v);
        }
#pragma unroll
        for (int s = 16; s > 0; s >>= 1)
            lmax = fmaxf(lmax, __shfl_xor_sync(0xffffffffu, lmax, s));

        float lsum = 0.f;
        for (int j = lane; j < cnt; j += 32) {
            float ex = __expf(p[j] - lmax);
            p[j] = ex;
            lsum += ex;
        }
#pragma unroll
        for (int s = 16; s > 0; s >>= 1)
            lsum += __shfl_xor_sync(0xffffffffu, lsum, s);
        __syncwarp();

        if (lane < NC) {
            float part = 0.f;
            for (int j = 0; j < cnt; ++j)
                part += p[j] * g_Who[(size_t)nb[j] * NC + lane];
            acc += ((hop ? 0.9f : 1.0f) / lsum) * part;
        }
        __syncwarp();
    }

    // ELU then log_softmax over 16 classes (lanes 0..15)
    float v = (lane < NC) ? (acc > 0.f ? acc : (__expf(acc) - 1.f)) : -1e30f;
    float mx = v;
#pragma unroll
    for (int s = 8; s > 0; s >>= 1)
        mx = fmaxf(mx, __shfl_xor_sync(0xffffffffu, mx, s));
    float ex = (lane < NC) ? __expf(v - mx) : 0.f;
    float sum = ex;
#pragma unroll
    for (int s = 8; s > 0; s >>= 1)
        sum += __shfl_xor_sync(0xffffffffu, sum, s);
    if (lane < NC)
        out[(size_t)n * NC + lane] = v - mx - __logf(sum);
}

// ---------------- launch ----------------------------------------------------
extern "C" void kernel_launch(void* const* d_in, const int* in_sizes, int n_in,
                              void* d_out, int out_size) {
    const float* x      = (const float*)d_in[0];
    const void*  masks  = (const void*) d_in[1];
    const float* W      = (const float*)d_in[2];
    const float* a1     = (const float*)d_in[3];
    const float* a2     = (const float*)d_in[4];
    const float* W_out  = (const float*)d_in[5];
    const float* a_out1 = (const float*)d_in[6];
    const float* a_out2 = (const float*)d_in[7];
    float* out = (float*)d_out;

    detect_mask_kernel<<<1, 1>>>(masks);
    build_nbr_kernel<<<(KH * NN * 32 + 255) / 256, 256>>>(masks);
    wh_gemm_kernel<<<dim3(NN / BM, NH), 256>>>(x, W);
    f12_kernel<<<(NH * NN + 255) / 256, 256>>>(a1, a2);
    gat1_kernel<<<NH * NN, 64>>>();
    who_kernel<<<NN, 128>>>(W_out, a_out1, a_out2);
    out_kernel<<<NN, 32>>>(out);
}

// round 2
// speedup vs baseline: 1.3440x; 1.3440x over previous
#include <cuda_runtime.h>
#include <cuda_bf16.h>
#include <cstdint>
#include <cstddef>

#define NN   4096
#define FIN  512
#define DH   64
#define NH   8
#define NC   16
#define KH   2
#define MAXNBR 512

typedef unsigned long long ull;

// ---------------- scratch ----------------------------------------------------
__device__ __nv_bfloat162 g_Whb[(size_t)NH * NN * (DH / 2)]; // [H,N,D] bf16 (4 MB)
__device__ float g_f1[NH * NN];
__device__ float g_f2[NH * NN];
__device__ float g_x2[(size_t)NN * NH * DH];                 // [N, H*D] (8 MB)
__device__ float g_Who[NN * NC];
__device__ float g_g1[NN];
__device__ float g_g2[NN];
__device__ int   g_nbr[(size_t)KH * NN * MAXNBR];
__device__ int   g_cnt[KH * NN];
__device__ int   g_mask_mode;                                // 0=byte, 1=word

// ---------------- f32x2 helpers ----------------------------------------------
__device__ __forceinline__ void fma2(ull& d, ull a, ull b) {
    asm("fma.rn.f32x2 %0, %1, %2, %0;" : "+l"(d) : "l"(a), "l"(b));
}
__device__ __forceinline__ ull pack2(float x, float y) {
    ull r; asm("mov.b64 %0, {%1, %2};" : "=l"(r) : "f"(x), "f"(y)); return r;
}
__device__ __forceinline__ float2 unpack2(ull v) {
    float2 r; asm("mov.b64 {%0, %1}, %2;" : "=f"(r.x), "=f"(r.y) : "l"(v)); return r;
}

// ---------------- mask dtype detection (self-loop diagonal is always 1) ------
__global__ void detect_mask_kernel(const void* m) {
    int i = threadIdx.x;                       // 32 threads
    const unsigned char* b = (const unsigned char*)m;
    bool okb = (b[(size_t)i * NN + i] == 1);
    unsigned bal = __ballot_sync(0xffffffffu, okb);
    if (i == 0) g_mask_mode = (bal == 0xffffffffu) ? 0 : 1;
}

// ---------------- neighbor list build (vectorized ballot compaction) ---------
__global__ void build_nbr_kernel(const void* m) {
    const int gw   = (blockIdx.x * blockDim.x + threadIdx.x) >> 5;
    const int lane = threadIdx.x & 31;
    if (gw >= KH * NN) return;
    int* nb = g_nbr + (size_t)gw * MAXNBR;
    int cnt = 0;

    if (g_mask_mode == 0) {
        const uint4* p = (const uint4*)((const unsigned char*)m + (size_t)gw * NN);
#pragma unroll
        for (int it = 0; it < NN / 512; ++it) {
            uint4 v = p[it * 32 + lane];
            unsigned w[4] = {v.x, v.y, v.z, v.w};
            int base = it * 512 + lane * 16;
#pragma unroll
            for (int q = 0; q < 4; ++q)
#pragma unroll
                for (int bp = 0; bp < 4; ++bp) {
                    bool mv = ((w[q] >> (8 * bp)) & 0xffu) != 0u;
                    unsigned bal = __ballot_sync(0xffffffffu, mv);
                    if (mv) {
                        int pos = cnt + __popc(bal & ((1u << lane) - 1u));
                        if (pos < MAXNBR) nb[pos] = base + q * 4 + bp;
                    }
                    cnt += __popc(bal);
                }
        }
    } else {
        const uint4* p = (const uint4*)((const unsigned*)m + (size_t)gw * NN);
#pragma unroll 4
        for (int it = 0; it < NN / 128; ++it) {
            uint4 v = p[it * 32 + lane];
            unsigned w[4] = {v.x, v.y, v.z, v.w};
            int base = it * 128 + lane * 4;
#pragma unroll
            for (int q = 0; q < 4; ++q) {
                bool mv = (w[q] != 0u);
                unsigned bal = __ballot_sync(0xffffffffu, mv);
                if (mv) {
                    int pos = cnt + __popc(bal & ((1u << lane) - 1u));
                    if (pos < MAXNBR) nb[pos] = base + q;
                }
                cnt += __popc(bal);
            }
        }
    }
    if (lane == 0) g_cnt[gw] = cnt < MAXNBR ? cnt : MAXNBR;
}

// ---------------- Wh = x @ W (bf16 out) + fused f1/f2, FFMA2 inner loop ------
#define GBM 128
#define GBK 32
__global__ void __launch_bounds__(128) wh_gemm_kernel(
        const float* __restrict__ x, const float* __restrict__ W,
        const float* __restrict__ a1v, const float* __restrict__ a2v) {
    const int h = blockIdx.y, row0 = blockIdx.x * GBM;
    const int tid = threadIdx.x;
    const int tx = tid & 7;           // col group: cols tx*8 .. +7
    const int ty = tid >> 3;          // row group: rows ty*8 .. +7

    __shared__ ull   xsd[GBK][GBM];   // duplicated-pair x: 32 KB
    __shared__ float ws [GBK][DH];    // 8 KB

    ull acc[8][4];
#pragma unroll
    for (int i = 0; i < 8; ++i)
#pragma unroll
        for (int j = 0; j < 4; ++j) acc[i][j] = 0ULL;

    for (int k0 = 0; k0 < FIN; k0 += GBK) {
        // load x tile transposed+duplicated: xsd[kk][r] = (x[r,kk], x[r,kk])
#pragma unroll
        for (int pass = 0; pass < 4; ++pass) {
            int r = pass * 32 + (tid >> 2);
            int seg = tid & 3;
            const float4* xp = (const float4*)(x + (size_t)(row0 + r) * FIN + k0 + seg * 8);
            float4 v0 = xp[0], v1 = xp[1];
            xsd[seg * 8 + 0][r] = pack2(v0.x, v0.x);
            xsd[seg * 8 + 1][r] = pack2(v0.y, v0.y);
            xsd[seg * 8 + 2][r] = pack2(v0.z, v0.z);
            xsd[seg * 8 + 3][r] = pack2(v0.w, v0.w);
            xsd[seg * 8 + 4][r] = pack2(v1.x, v1.x);
            xsd[seg * 8 + 5][r] = pack2(v1.y, v1.y);
            xsd[seg * 8 + 6][r] = pack2(v1.z, v1.z);
            xsd[seg * 8 + 7][r] = pack2(v1.w, v1.w);
        }
        // load W tile
        {
            int s = tid;
#pragma unroll
            for (int rep = 0; rep < 4; ++rep, s += 128) {
                int kk = s >> 4, c4 = (s & 15) * 4;
                float4 v = *(const float4*)(W + ((size_t)h * FIN + k0 + kk) * DH + c4);
                *(float4*)&ws[kk][c4] = v;
            }
        }
        __syncthreads();
#pragma unroll
        for (int kk = 0; kk < GBK; ++kk) {
            ull a[8];
            *(ulonglong2*)&a[0] = *(const ulonglong2*)&xsd[kk][ty * 8 + 0];
            *(ulonglong2*)&a[2] = *(const ulonglong2*)&xsd[kk][ty * 8 + 2];
            *(ulonglong2*)&a[4] = *(const ulonglong2*)&xsd[kk][ty * 8 + 4];
            *(ulonglong2*)&a[6] = *(const ulonglong2*)&xsd[kk][ty * 8 + 6];
            ull b[4];
            *(ulonglong2*)&b[0] = *(const ulonglong2*)&ws[kk][tx * 8 + 0];
            *(ulonglong2*)&b[2] = *(const ulonglong2*)&ws[kk][tx * 8 + 4];
#pragma unroll
            for (int i = 0; i < 8; ++i)
#pragma unroll
                for (int j = 0; j < 4; ++j)
                    fma2(acc[i][j], a[i], b[j]);
        }
        __syncthreads();
    }

    // epilogue: bf16 Wh store + fused f1/f2 partials
    const float* A1 = a1v + h * DH + tx * 8;
    const float* A2 = a2v + h * DH + tx * 8;
    float a1r[8], a2r[8];
#pragma unroll
    for (int c = 0; c < 8; ++c) { a1r[c] = A1[c]; a2r[c] = A2[c]; }

    float* f1s = (float*)xsd;          // reuse smem (8 groups x 128 rows)
    float* f2s = f1s + 1024;

#pragma unroll
    for (int i = 0; i < 8; ++i) {
        float v[8];
#pragma unroll
        for (int j = 0; j < 4; ++j) {
            float2 u = unpack2(acc[i][j]);
            v[2 * j] = u.x; v[2 * j + 1] = u.y;
        }
        int row = row0 + ty * 8 + i;
        __nv_bfloat162* dst = g_Whb + ((size_t)h * NN + row) * 32 + tx * 4;
        dst[0] = __floats2bfloat162_rn(v[0], v[1]);
        dst[1] = __floats2bfloat162_rn(v[2], v[3]);
        dst[2] = __floats2bfloat162_rn(v[4], v[5]);
        dst[3] = __floats2bfloat162_rn(v[6], v[7]);
        float p1 = 0.f, p2 = 0.f;
#pragma unroll
        for (int c = 0; c < 8; ++c) { p1 += v[c] * a1r[c]; p2 += v[c] * a2r[c]; }
        f1s[tx * 128 + ty * 8 + i] = p1;
        f2s[tx * 128 + ty * 8 + i] = p2;
    }
    __syncthreads();
    {
        int r = tid;
        float s1 = 0.f, s2 = 0.f;
#pragma unroll
        for (int g = 0; g < 8; ++g) { s1 += f1s[g * 128 + r]; s2 += f2s[g * 128 + r]; }
        g_f1[h * NN + row0 + r] = s1;
        g_f2[h * NN + row0 + r] = s2;
    }
}

// ---------------- layer-1 sparse k-hop attention ------------------------------
__global__ void __launch_bounds__(128) gat1_kernel() {
    const int b = blockIdx.x;
    const int h = b >> 12;
    const int n = b & 4095;
    const int t = threadIdx.x, wi = t >> 5, lane = t & 31;

    __shared__ float  p[MAXNBR];
    __shared__ int    nbs[MAXNBR];
    __shared__ float  red[4];
    __shared__ float2 accs[128];

    const float  f1v = g_f1[h * NN + n];
    const float* f2h = g_f2 + h * NN;
    const __nv_bfloat162* WhH = g_Whb + (size_t)h * NN * 32;

    float2 tot = make_float2(0.f, 0.f);
    for (int hop = 0; hop < KH; ++hop) {
        const int  w   = hop * NN + n;
        const int  cnt = g_cnt[w];
        const int* nbg = g_nbr + (size_t)w * MAXNBR;

        float lsum = 0.f;
        for (int j = t; j < cnt; j += 128) {
            int nbj = nbg[j];
            nbs[j] = nbj;
            float v = f1v + f2h[nbj];
            v = v > 0.f ? v : 0.2f * v;
            float ex = __expf(v);         // bounded e: no max pass needed
            p[j] = ex;
            lsum += ex;
        }
#pragma unroll
        for (int s = 16; s > 0; s >>= 1)
            lsum += __shfl_xor_sync(0xffffffffu, lsum, s);
        if (lane == 0) red[wi] = lsum;
        __syncthreads();
        const float scale = (hop ? 0.9f : 1.0f) / (red[0] + red[1] + red[2] + red[3]);

        float2 part = make_float2(0.f, 0.f);
        for (int j = wi; j < cnt; j += 4) {
            float wgt = p[j];
            float2 f = __bfloat1622float2(WhH[(size_t)nbs[j] * 32 + lane]);
            part.x += wgt * f.x;
            part.y += wgt * f.y;
        }
        tot.x += scale * part.x;
        tot.y += scale * part.y;
        __syncthreads();
    }
    accs[t] = tot;
    __syncthreads();
    if (wi == 0) {
        float2 r0 = accs[lane], r1 = accs[32 + lane], r2 = accs[64 + lane], r3 = accs[96 + lane];
        float vx = r0.x + r1.x + r2.x + r3.x;
        float vy = r0.y + r1.y + r2.y + r3.y;
        vx = vx > 0.f ? vx : (__expf(vx) - 1.f);
        vy = vy > 0.f ? vy : (__expf(vy) - 1.f);
        *(float2*)(g_x2 + (size_t)n * (NH * DH) + h * DH + 2 * lane) = make_float2(vx, vy);
    }
}

// ---------------- Who = x2 @ W_out (+ g1,g2), W_out in smem --------------------
__global__ void __launch_bounds__(512) who_kernel(
        const float* __restrict__ W_out,
        const float* __restrict__ ao1, const float* __restrict__ ao2) {
    const int g = threadIdx.x >> 7;            // row slot 0..3
    const int t = threadIdx.x & 127;
    const int r = blockIdx.x * 4 + g;

    __shared__ float xs[4][FIN];
    __shared__ float wsh[FIN * NC];            // 32 KB? no: 512*16*4 = 32 KB
    __shared__ float wsum[4][128];
    __shared__ float who_s[4][NC];

    // stage W_out (8192 floats) once per block
    for (int i = threadIdx.x; i < FIN * NC / 4; i += 512)
        *(float4*)&wsh[i * 4] = *(const float4*)&W_out[i * 4];
    ((float4*)xs[g])[t] = ((const float4*)(g_x2 + (size_t)r * FIN))[t];
    __syncthreads();

    const int c = t & 15, ks = t >> 4;
    float s = 0.f;
    for (int k = ks; k < FIN; k += 8)
        s += xs[g][k] * wsh[k * NC + c];
    wsum[g][t] = s;
    __syncthreads();

    if (t < NC) {
        float tot = 0.f;
#pragma unroll
        for (int i = 0; i < 8; ++i) tot += wsum[g][i * 16 + t];
        who_s[g][t] = tot;
        g_Who[(size_t)r * NC + t] = tot;
    }
    __syncthreads();
    if (t == 0) {
        float gg = 0.f;
#pragma unroll
        for (int cc = 0; cc < NC; ++cc) gg += who_s[g][cc] * ao1[cc];
        g_g1[r] = gg;
    }
    if (t == 1) {
        float gg = 0.f;
#pragma unroll
        for (int cc = 0; cc < NC; ++cc) gg += who_s[g][cc] * ao2[cc];
        g_g2[r] = gg;
    }
}

// ---------------- output sparse attention + elu + log_softmax ------------------
__global__ void __launch_bounds__(32) out_kernel(float* __restrict__ out) {
    const int n = blockIdx.x;
    const int lane = threadIdx.x;
    const int c = lane & 15, half = lane >> 4;

    __shared__ float p[MAXNBR];
    __shared__ int   nbs[MAXNBR];

    const float g1v = g_g1[n];
    float acc = 0.f;

    for (int hop = 0; hop < KH; ++hop) {
        const int  w   = hop * NN + n;
        const int  cnt = g_cnt[w];
        const int* nbg = g_nbr + (size_t)w * MAXNBR;

        float lsum = 0.f;
        for (int j = lane; j < cnt; j += 32) {
            int nbj = nbg[j];
            nbs[j] = nbj;
            float v = g1v + g_g2[nbj];
            v = v > 0.f ? v : 0.2f * v;
            float ex = __expf(v);
            p[j] = ex;
            lsum += ex;
        }
#pragma unroll
        for (int s = 16; s > 0; s >>= 1)
            lsum += __shfl_xor_sync(0xffffffffu, lsum, s);
        __syncwarp();

        float part = 0.f;
        for (int j = half; j < cnt; j += 2)
            part += p[j] * g_Who[(size_t)nbs[j] * NC + c];
        acc += ((hop ? 0.9f : 1.0f) / lsum) * part;
        __syncwarp();
    }
    acc += __shfl_xor_sync(0xffffffffu, acc, 16);   // combine the two halves

    float v = acc > 0.f ? acc : (__expf(acc) - 1.f);
    float mx = v;
#pragma unroll
    for (int s = 8; s > 0; s >>= 1)
        mx = fmaxf(mx, __shfl_xor_sync(0xffffffffu, mx, s));
    float ex = __expf(v - mx);
    float sum = ex;
#pragma unroll
    for (int s = 8; s > 0; s >>= 1)
        sum += __shfl_xor_sync(0xffffffffu, sum, s);
    if (lane < NC)
        out[(size_t)n * NC + lane] = v - mx - __logf(sum);
}

// ---------------- launch --------------------------------------------------------
extern "C" void kernel_launch(void* const* d_in, const int* in_sizes, int n_in,
                              void* d_out, int out_size) {
    const float* x      = (const float*)d_in[0];
    const void*  masks  = (const void*) d_in[1];
    const float* W      = (const float*)d_in[2];
    const float* a1     = (const float*)d_in[3];
    const float* a2     = (const float*)d_in[4];
    const float* W_out  = (const float*)d_in[5];
    const float* ao1    = (const float*)d_in[6];
    const float* ao2    = (const float*)d_in[7];
    float* out = (float*)d_out;

    detect_mask_kernel<<<1, 32>>>(masks);
    build_nbr_kernel<<<(KH * NN * 32) / 256, 256>>>(masks);
    wh_gemm_kernel<<<dim3(NN / GBM, NH), 128>>>(x, W, a1, a2);
    gat1_kernel<<<NH * NN, 128>>>();
    who_kernel<<<NN / 4, 512>>>(W_out, ao1, ao2);
    out_kernel<<<NN, 32>>>(out);
}